// round 6
// baseline (speedup 1.0000x reference)
#include <cuda_runtime.h>
#include <math.h>

#define T_LEN 32
#define KP    2048
#define WPB   14                      // warps (=columns) per block
#define BLOCK (WPB * 32)              // 448
#define GRID  ((KP + WPB - 1) / WPB)  // 147

// sp = sqrt(1/32); 0.5/sp^2 = 16 exactly
#define LOG_SP     (-1.7328679513998633f)
#define HALF_L2PI  (0.9189385332046727f)
#define LOG_K      (7.6246189861593985f)
#define C2EXP      (-23.083120654223414f)   // -16 * log2(e)
#define L2E        (1.4426950408889634f)
#define D2CLAMP    (5.40f)                  // -16*log2e*5.4 > -126: term == 0 anyway
#define F_INF      (__int_as_float(0x7f800000))

__device__ float g_zs[T_LEN * KP];
__device__ float g_A [T_LEN * KP];
__device__ float g_r [2][KP];
__device__ int   g_xmax[T_LEN];   // order-encoded float max of r at step t

// order-preserving float<->int encoding for atomicMax
__device__ __forceinline__ int   fenc(float f) { int b = __float_as_int(f); return b >= 0 ? b : (b ^ 0x7fffffff); }
__device__ __forceinline__ float fdec(int e)   { return __int_as_float(e >= 0 ? e : (e ^ 0x7fffffff)); }

// scalar fast 2^t for t <= 0 (clamped), FMA/ALU pipes only
__device__ __forceinline__ float fexp2(float t) {
    t = fmaxf(t, -126.0f);
    float fn = t + 12582912.0f;
    int   n  = __float_as_int(fn) - 0x4B400000;
    float f  = t - (fn - 12582912.0f);
    float p  = 1.3398874e-3f;
    p = fmaf(p, f, 9.6184374e-3f);
    p = fmaf(p, f, 5.5503325e-2f);
    p = fmaf(p, f, 2.4022648e-1f);
    p = fmaf(p, f, 6.9314720e-1f);
    p = fmaf(p, f, 1.0f);
    return __int_as_float(__float_as_int(p) + (n << 23));
}

// packed f32x2 ops (sm_103a)
#define F2ADD(o,a,b)   asm("add.rn.f32x2 %0,%1,%2;"    : "=l"(o) : "l"(a), "l"(b))
#define F2MUL(o,a,b)   asm("mul.rn.f32x2 %0,%1,%2;"    : "=l"(o) : "l"(a), "l"(b))
#define F2FMA(o,a,b,c) asm("fma.rn.f32x2 %0,%1,%2,%3;" : "=l"(o) : "l"(a), "l"(b), "l"(c))

__device__ __forceinline__ unsigned long long f2pk(float lo, float hi) {
    unsigned long long r; asm("mov.b64 %0,{%1,%2};" : "=l"(r) : "f"(lo), "f"(hi)); return r;
}
__device__ __forceinline__ unsigned long long u2pk(unsigned lo, unsigned hi) {
    unsigned long long r; asm("mov.b64 %0,{%1,%2};" : "=l"(r) : "r"(lo), "r"(hi)); return r;
}

__global__ void init_kernel() {
    int i = threadIdx.x;
    if (i < T_LEN) g_xmax[i] = fenc(-F_INF);
}

// Setup: zs = mu + sigma*eps; A[t,k] = -log(sp)-0.5log2pi-log_q; r0; max(r0)
__global__ void setup_kernel(const float* __restrict__ means,
                             const float* __restrict__ log_stds,
                             const float* __restrict__ eps) {
    int idx = blockIdx.x * blockDim.x + threadIdx.x;   // grid covers exactly T_LEN*KP
    int t = idx / KP;
    int k = idx - t * KP;
    float mu = means[t];
    float s  = expf(log_stds[t]);
    float e  = eps[idx];
    float z  = fmaf(s, e, mu);
    float zq = (z - mu) / s;
    float lq = fmaf(-0.5f * zq, zq, -logf(s)) - HALF_L2PI;
    g_zs[idx] = z;
    g_A[idx]  = -LOG_SP - HALF_L2PI - lq;
    if (t == 0) {
        float zz = z * 5.656854249492380f;   // z / sp
        float r0 = fmaf(-0.5f * zz, zz, -LOG_SP) - HALF_L2PI - lq;
        g_r[0][k] = r0;
        float m = r0;
        #pragma unroll
        for (int sft = 16; sft; sft >>= 1)
            m = fmaxf(m, __shfl_xor_sync(0xffffffffu, m, sft));
        if ((threadIdx.x & 31) == 0) atomicMax(&g_xmax[0], fenc(m));
    }
}

// One scan step: r_out[k] = x + a_k + log(sum_j u_j * exp(-16 d^2)) - logK
__global__ void __launch_bounds__(BLOCK) step_kernel(int t) {
    __shared__ __align__(16) float zp[KP];   // holds -z_prev
    __shared__ __align__(16) float uw[KP];   // u_j = exp(r_j - x)
    __shared__ float wred[WPB];

    const int tid  = threadIdx.x;
    const int wid  = tid >> 5;
    const int lane = tid & 31;
    const float* __restrict__ r_in  = g_r[(t - 1) & 1];
    float*       __restrict__ r_out = g_r[t & 1];
    const float* __restrict__ zrow  = g_zs + (t - 1) * KP;

    const float x = fdec(g_xmax[t - 1]);
    for (int j = tid; j < KP; j += BLOCK) {
        float rv = r_in[j];
        uw[j] = fexp2((rv - x) * L2E);
        zp[j] = -zrow[j];
    }
    __syncthreads();

    const int k = blockIdx.x * WPB + wid;
    if (k < KP) {
        const float zk = g_zs[t * KP + k];
        const float ak = g_A[t * KP + k];
        const unsigned long long zk2  = f2pk(zk, zk);
        const unsigned long long c2v  = f2pk(C2EXP, C2EXP);
        const unsigned long long bigv = f2pk(12582912.0f, 12582912.0f);
        const unsigned long long nbgv = f2pk(-12582912.0f, -12582912.0f);
        const unsigned long long m1v  = f2pk(-1.0f, -1.0f);
        const unsigned long long c5v  = f2pk(1.3398874e-3f, 1.3398874e-3f);
        const unsigned long long c4v  = f2pk(9.6184374e-3f, 9.6184374e-3f);
        const unsigned long long c3v  = f2pk(5.5503325e-2f, 5.5503325e-2f);
        const unsigned long long c2pv = f2pk(2.4022648e-1f, 2.4022648e-1f);
        const unsigned long long c1v  = f2pk(6.9314720e-1f, 6.9314720e-1f);
        const unsigned long long c0v  = f2pk(1.0f, 1.0f);

        unsigned long long S2 = 0ULL;
        #pragma unroll 4
        for (int i = 0; i < KP / 64; i++) {
            int jj = i * 32 + lane;                      // float2 index
            unsigned long long zu = *reinterpret_cast<const unsigned long long*>(zp + 2 * jj);
            unsigned long long uu = *reinterpret_cast<const unsigned long long*>(uw + 2 * jj);
            unsigned long long d, dd, tt, fn, nn, f, p;
            F2ADD(d, zk2, zu);                           // d = zk - z'
            F2MUL(dd, d, d);
            float d0 = fminf(__uint_as_float((unsigned)dd),         D2CLAMP);
            float d1 = fminf(__uint_as_float((unsigned)(dd >> 32)), D2CLAMP);
            dd = f2pk(d0, d1);
            F2MUL(tt, dd, c2v);                          // t in [-125.9, 0]
            F2ADD(fn, tt, bigv);
            F2ADD(nn, fn, nbgv);                         // n = round(t)
            F2FMA(f, nn, m1v, tt);                       // f = t - n
            F2FMA(p, c5v, f, c4v);
            F2FMA(p, p,   f, c3v);
            F2FMA(p, p,   f, c2pv);
            F2FMA(p, p,   f, c1v);
            F2FMA(p, p,   f, c0v);                       // p ~= 2^f
            unsigned fnl = (unsigned)fn, fnh = (unsigned)(fn >> 32);
            unsigned pl  = (unsigned)p,  ph  = (unsigned)(p  >> 32);
            unsigned long long ev = u2pk(pl + (fnl << 23), ph + (fnh << 23));  // 2^f * 2^n
            F2FMA(S2, uu, ev, S2);
        }
        float S = __uint_as_float((unsigned)S2) + __uint_as_float((unsigned)(S2 >> 32));
        #pragma unroll
        for (int m = 16; m; m >>= 1)
            S += __shfl_xor_sync(0xffffffffu, S, m);
        if (lane == 0) {
            float val = x + ak + logf(fmaxf(S, 1e-37f)) - LOG_K;
            r_out[k]  = val;
            wred[wid] = val;
        }
    } else if (lane == 0) {
        wred[wid] = -F_INF;
    }
    __syncthreads();
    if (tid == 0) {
        float m = wred[0];
        #pragma unroll
        for (int w = 1; w < WPB; w++) m = fmaxf(m, wred[w]);
        atomicMax(&g_xmax[t], fenc(m));
    }
}

// Final: out = x + y + log(sum_j exp(r_j - x)*exp(L_j - y)) - logK
__global__ void final_kernel(float* __restrict__ out) {
    __shared__ float sr[KP];
    __shared__ float sL[KP];
    __shared__ float red[32];
    const int tid = threadIdx.x;
    const float* __restrict__ zrow = g_zs + (T_LEN - 1) * KP;
    const float* __restrict__ rv   = g_r[(T_LEN - 1) & 1];

    float lr = -F_INF, lL = -F_INF;
    #pragma unroll
    for (int i = 0; i < KP / 256; i++) {
        int j = tid + i * 256;
        float r = rv[j];
        float z = zrow[j];
        float dd = 0.5f - z;
        float Lv = fmaf(-0.5f * dd, dd, -HALF_L2PI);
        sr[j] = r; sL[j] = Lv;
        lr = fmaxf(lr, r);
        lL = fmaxf(lL, Lv);
    }
    #pragma unroll
    for (int m = 16; m; m >>= 1) {
        lr = fmaxf(lr, __shfl_xor_sync(0xffffffffu, lr, m));
        lL = fmaxf(lL, __shfl_xor_sync(0xffffffffu, lL, m));
    }
    if ((tid & 31) == 0) { red[tid >> 5] = lr; red[8 + (tid >> 5)] = lL; }
    __syncthreads();
    float x = red[0], y = red[8];
    #pragma unroll
    for (int w = 1; w < 8; w++) { x = fmaxf(x, red[w]); y = fmaxf(y, red[8 + w]); }

    float S = 0.0f;
    #pragma unroll
    for (int i = 0; i < KP / 256; i++) {
        int j = tid + i * 256;
        S += fexp2(((sr[j] - x) + (sL[j] - y)) * L2E);
    }
    #pragma unroll
    for (int m = 16; m; m >>= 1)
        S += __shfl_xor_sync(0xffffffffu, S, m);
    if ((tid & 31) == 0) red[16 + (tid >> 5)] = S;
    __syncthreads();
    if (tid == 0) {
        float tot = 0.0f;
        #pragma unroll
        for (int w = 0; w < 8; w++) tot += red[16 + w];
        out[0] = x + y + logf(tot) - LOG_K;
    }
}

extern "C" void kernel_launch(void* const* d_in, const int* in_sizes, int n_in,
                              void* d_out, int out_size) {
    const float* means    = (const float*)d_in[0];
    const float* log_stds = (const float*)d_in[1];
    const float* eps      = (const float*)d_in[2];
    float* out = (float*)d_out;

    init_kernel<<<1, 32>>>();
    setup_kernel<<<(T_LEN * KP) / 256, 256>>>(means, log_stds, eps);
    for (int t = 1; t < T_LEN; t++)
        step_kernel<<<GRID, BLOCK>>>(t);
    final_kernel<<<1, 256>>>(out);
}